// round 1
// baseline (speedup 1.0000x reference)
#include <cuda_runtime.h>
#include <cuda_bf16.h>

#define NN 50000
#define EE 600000
#define DD 128
#define LL 4
#define GG 128

// ---------------- scratch (device globals; no allocation) ----------------
static __device__ float g_deg[NN];
static __device__ float g_dinv[NN];
static __device__ float g_coef[EE];
static __device__ float g_xc[NN * DD];   // current features
static __device__ float g_h[NN * DD];    // x @ W
static __device__ float g_agg[NN * DD];  // scatter accumulator
static __device__ float g_sums[GG * DD];
static __device__ float g_cnt[GG];

// ---------------- init: zero deg, pool sums/cnt ----------------
__global__ void k_init() {
    int i = blockIdx.x * blockDim.x + threadIdx.x;
    if (i < NN) g_deg[i] = 0.f;
    if (i < GG * DD) g_sums[i] = 0.f;
    if (i < GG) g_cnt[i] = 0.f;
}

// ---------------- degree count ----------------
__global__ void k_deg(const int* __restrict__ dst) {
    int e = blockIdx.x * blockDim.x + threadIdx.x;
    if (e < EE) atomicAdd(&g_deg[dst[e]], 1.0f);
}

__global__ void k_dinv() {
    int n = blockIdx.x * blockDim.x + threadIdx.x;
    if (n < NN) g_dinv[n] = rsqrtf(g_deg[n] + 1.0f);
}

__global__ void k_copy(const float* __restrict__ x) {
    int i = blockIdx.x * blockDim.x + threadIdx.x;  // float4 index
    if (i < NN * DD / 4)
        ((float4*)g_xc)[i] = ((const float4*)x)[i];
}

__global__ void k_coef(const int* __restrict__ src, const int* __restrict__ dst) {
    int e = blockIdx.x * blockDim.x + threadIdx.x;
    if (e < EE) g_coef[e] = g_dinv[src[e]] * g_dinv[dst[e]];
}

// ---------------- GEMM: h = xc @ W[l], also zero agg ----------------
#define BM 64
#define BK 32
__global__ void k_gemm(const float* __restrict__ Wl) {
    __shared__ float Xs[BM][BK + 1];
    __shared__ float Ws[BK][DD];
    int tid = threadIdx.x;
    int row0 = blockIdx.x * BM;
    int tx = tid & 31;   // col group: cols [tx*4, tx*4+4)
    int ty = tid >> 5;   // row group: rows [ty*8, ty*8+8)

    float acc[8][4];
#pragma unroll
    for (int i = 0; i < 8; i++)
#pragma unroll
        for (int j = 0; j < 4; j++) acc[i][j] = 0.f;

    for (int k0 = 0; k0 < DD; k0 += BK) {
        // load X tile (BM x BK)
#pragma unroll
        for (int i = 0; i < (BM * BK) / 256; i++) {
            int idx = tid + i * 256;
            int r = idx >> 5;       // /BK
            int kk = idx & 31;
            int gr = row0 + r;
            Xs[r][kk] = (gr < NN) ? g_xc[gr * DD + k0 + kk] : 0.f;
        }
        // load W tile (BK x DD)
#pragma unroll
        for (int i = 0; i < (BK * DD) / 256; i++) {
            int idx = tid + i * 256;
            int kk = idx >> 7;      // /DD
            int j = idx & 127;
            Ws[kk][j] = Wl[(k0 + kk) * DD + j];
        }
        __syncthreads();
#pragma unroll
        for (int k = 0; k < BK; k++) {
            float4 wv = *(const float4*)&Ws[k][tx * 4];
#pragma unroll
            for (int i = 0; i < 8; i++) {
                float a = Xs[ty * 8 + i][k];
                acc[i][0] += a * wv.x;
                acc[i][1] += a * wv.y;
                acc[i][2] += a * wv.z;
                acc[i][3] += a * wv.w;
            }
        }
        __syncthreads();
    }
#pragma unroll
    for (int i = 0; i < 8; i++) {
        int r = row0 + ty * 8 + i;
        if (r < NN) {
            float4 v = make_float4(acc[i][0], acc[i][1], acc[i][2], acc[i][3]);
            *(float4*)&g_h[r * DD + tx * 4] = v;
            *(float4*)&g_agg[r * DD + tx * 4] = make_float4(0.f, 0.f, 0.f, 0.f);
        }
    }
}

// ---------------- edge scatter: agg[dst] += h[src] * coef ----------------
__global__ void k_scatter(const int* __restrict__ src, const int* __restrict__ dst) {
    int warp = (blockIdx.x * blockDim.x + threadIdx.x) >> 5;
    if (warp >= EE) return;
    int lane = threadIdx.x & 31;
    int s = src[warp];
    int d = dst[warp];
    float c = g_coef[warp];
    float4 hv = *(const float4*)&g_h[s * DD + lane * 4];
    float* ap = &g_agg[d * DD + lane * 4];
    atomicAdd(ap + 0, hv.x * c);
    atomicAdd(ap + 1, hv.y * c);
    atomicAdd(ap + 2, hv.z * c);
    atomicAdd(ap + 3, hv.w * c);
}

// ---------------- residual + bias + LayerNorm + ReLU ----------------
__global__ void k_update(const float* __restrict__ bl,
                         const float* __restrict__ gl,
                         const float* __restrict__ betal) {
    int warp = (blockIdx.x * blockDim.x + threadIdx.x) >> 5;
    if (warp >= NN) return;
    int lane = threadIdx.x & 31;
    int n = warp;
    float di = g_dinv[n];
    float self = di * di;
    int base = n * DD + lane * 4;

    float4 xv = *(const float4*)&g_xc[base];
    float4 av = *(const float4*)&g_agg[base];
    float4 hv = *(const float4*)&g_h[base];
    float4 bv = *(const float4*)&bl[lane * 4];

    float v[4];
    v[0] = xv.x + av.x + hv.x * self + bv.x;
    v[1] = xv.y + av.y + hv.y * self + bv.y;
    v[2] = xv.z + av.z + hv.z * self + bv.z;
    v[3] = xv.w + av.w + hv.w * self + bv.w;

    float s = v[0] + v[1] + v[2] + v[3];
#pragma unroll
    for (int o = 16; o > 0; o >>= 1) s += __shfl_xor_sync(0xffffffffu, s, o);
    float m = s * (1.0f / DD);

    float d0 = v[0] - m, d1 = v[1] - m, d2 = v[2] - m, d3 = v[3] - m;
    float sq = d0 * d0 + d1 * d1 + d2 * d2 + d3 * d3;
#pragma unroll
    for (int o = 16; o > 0; o >>= 1) sq += __shfl_xor_sync(0xffffffffu, sq, o);
    float inv = rsqrtf(sq * (1.0f / DD) + 1e-5f);

    float4 gv = *(const float4*)&gl[lane * 4];
    float4 tv = *(const float4*)&betal[lane * 4];
    float4 out;
    out.x = fmaxf(d0 * inv * gv.x + tv.x, 0.f);
    out.y = fmaxf(d1 * inv * gv.y + tv.y, 0.f);
    out.z = fmaxf(d2 * inv * gv.z + tv.z, 0.f);
    out.w = fmaxf(d3 * inv * gv.w + tv.w, 0.f);
    *(float4*)&g_xc[base] = out;
}

// ---------------- global mean pool ----------------
__global__ void k_pool(const int* __restrict__ batch) {
    int warp = (blockIdx.x * blockDim.x + threadIdx.x) >> 5;
    if (warp >= NN) return;
    int lane = threadIdx.x & 31;
    int g = batch[warp];
    if (lane == 0) atomicAdd(&g_cnt[g], 1.0f);
    float4 xv = *(const float4*)&g_xc[warp * DD + lane * 4];
    float* sp = &g_sums[g * DD + lane * 4];
    atomicAdd(sp + 0, xv.x);
    atomicAdd(sp + 1, xv.y);
    atomicAdd(sp + 2, xv.z);
    atomicAdd(sp + 3, xv.w);
}

__global__ void k_out(float* __restrict__ out) {
    int i = blockIdx.x * blockDim.x + threadIdx.x;
    if (i < GG * DD) out[i] = g_sums[i] / fmaxf(g_cnt[i >> 7], 1.0f);
}

// ---------------- launch ----------------
extern "C" void kernel_launch(void* const* d_in, const int* in_sizes, int n_in,
                              void* d_out, int out_size) {
    const float* x = (const float*)d_in[0];
    const int* ei = (const int*)d_in[1];
    const int* batch = (const int*)d_in[2];
    const float* W = (const float*)d_in[3];
    const float* b = (const float*)d_in[4];
    const float* gamma = (const float*)d_in[5];
    const float* beta = (const float*)d_in[6];
    float* out = (float*)d_out;

    const int* src = ei;
    const int* dst = ei + EE;

    k_init<<<(NN + 255) / 256, 256>>>();
    k_deg<<<(EE + 255) / 256, 256>>>(dst);
    k_dinv<<<(NN + 255) / 256, 256>>>();
    k_copy<<<(NN * DD / 4 + 255) / 256, 256>>>(x);
    k_coef<<<(EE + 255) / 256, 256>>>(src, dst);

    for (int l = 0; l < LL; l++) {
        k_gemm<<<(NN + BM - 1) / BM, 256>>>(W + l * DD * DD);
        k_scatter<<<(EE * 32 + 255) / 256, 256>>>(src, dst);
        k_update<<<(NN * 32 + 255) / 256, 256>>>(b + l * DD, gamma + l * DD, beta + l * DD);
    }

    k_pool<<<(NN * 32 + 255) / 256, 256>>>(batch);
    k_out<<<(GG * DD + 255) / 256, 256>>>(out);
}

// round 5
// speedup vs baseline: 2.7544x; 2.7544x over previous
#include <cuda_runtime.h>
#include <cuda_bf16.h>

#define NN 50000
#define EE 600000
#define DD 128
#define LL 4
#define GG 128

// ---------------- scratch (device globals; referenced ONLY in device code) ----------------
static __device__ int   g_degi[NN];
static __device__ float g_dinv[NN];
static __device__ int   g_off[NN + 1];
static __device__ int   g_cursor[NN];
static __device__ int   g_bsum[64];
static __device__ int   g_esrc[EE];
static __device__ float g_ecoef[EE];
static __device__ float g_xc[NN * DD];   // current features (in-place per layer)
static __device__ float g_h[NN * DD];    // x @ W
static __device__ float g_sums[GG * DD];
static __device__ float g_cnt[GG];

// ---------------- init: zero histograms / pool ----------------
__global__ void k_init() {
    int i = blockIdx.x * blockDim.x + threadIdx.x;
    if (i < NN) { g_degi[i] = 0; g_cursor[i] = 0; }
    if (i < GG * DD) g_sums[i] = 0.f;
    if (i < GG) g_cnt[i] = 0.f;
}

__global__ void k_copy(const float* __restrict__ x) {
    int i = blockIdx.x * blockDim.x + threadIdx.x;  // float4 index
    if (i < NN * DD / 4)
        ((float4*)g_xc)[i] = ((const float4*)x)[i];
}

// ---------------- degree histogram (by dst) + graph-size histogram ----------------
__global__ void k_deg(const int* __restrict__ dst) {
    int e = blockIdx.x * blockDim.x + threadIdx.x;
    if (e < EE) atomicAdd(&g_degi[dst[e]], 1);
}

__global__ void k_cnt(const int* __restrict__ batch) {
    int n = blockIdx.x * blockDim.x + threadIdx.x;
    if (n < NN) atomicAdd(&g_cnt[batch[n]], 1.0f);
}

__global__ void k_dinv() {
    int n = blockIdx.x * blockDim.x + threadIdx.x;
    if (n < NN) g_dinv[n] = rsqrtf((float)g_degi[n] + 1.0f);
}

// ---------------- exclusive scan of g_degi -> g_off ----------------
#define SCB 1024
__global__ void k_scan1() {
    __shared__ int sh[SCB];
    int i = blockIdx.x * SCB + threadIdx.x;
    int v = (i < NN) ? g_degi[i] : 0;
    sh[threadIdx.x] = v;
    __syncthreads();
#pragma unroll
    for (int o = 1; o < SCB; o <<= 1) {
        int t = 0;
        if ((int)threadIdx.x >= o) t = sh[threadIdx.x - o];
        __syncthreads();
        if ((int)threadIdx.x >= o) sh[threadIdx.x] += t;
        __syncthreads();
    }
    if (i < NN) g_off[i] = sh[threadIdx.x] - v;  // exclusive within block
    if (threadIdx.x == SCB - 1) g_bsum[blockIdx.x] = sh[SCB - 1];
}

__global__ void k_scan2(int nblocks) {
    if (threadIdx.x == 0) {
        int run = 0;
        for (int b = 0; b < nblocks; b++) {
            int t = g_bsum[b];
            g_bsum[b] = run;
            run += t;
        }
    }
}

__global__ void k_scan3() {
    int i = blockIdx.x * SCB + threadIdx.x;
    if (i < NN) g_off[i] += g_bsum[blockIdx.x];
    if (i == NN) g_off[NN] = EE;
}

// ---------------- fill CSR: e_src, e_coef in dst-grouped order ----------------
__global__ void k_fill(const int* __restrict__ src, const int* __restrict__ dst) {
    int e = blockIdx.x * blockDim.x + threadIdx.x;
    if (e >= EE) return;
    int s = src[e], d = dst[e];
    int p = g_off[d] + atomicAdd(&g_cursor[d], 1);
    g_esrc[p] = s;
    g_ecoef[p] = g_dinv[s] * g_dinv[d];
}

// ---------------- GEMM: g_h = g_xc @ W[l] ----------------
#define BM 64
#define BK 32
__global__ void k_gemm(const float* __restrict__ Wl) {
    __shared__ float Xs[BM][BK + 1];
    __shared__ float Ws[BK][DD];
    int tid = threadIdx.x;
    int row0 = blockIdx.x * BM;
    int tx = tid & 31;   // cols [tx*4, tx*4+4)
    int ty = tid >> 5;   // rows [ty*8, ty*8+8)

    float acc[8][4];
#pragma unroll
    for (int i = 0; i < 8; i++)
#pragma unroll
        for (int j = 0; j < 4; j++) acc[i][j] = 0.f;

    for (int k0 = 0; k0 < DD; k0 += BK) {
#pragma unroll
        for (int i = 0; i < (BM * BK) / 256; i++) {
            int idx = tid + i * 256;
            int r = idx >> 5;
            int kk = idx & 31;
            int gr = row0 + r;
            Xs[r][kk] = (gr < NN) ? g_xc[gr * DD + k0 + kk] : 0.f;
        }
#pragma unroll
        for (int i = 0; i < (BK * DD) / 256; i++) {
            int idx = tid + i * 256;
            int kk = idx >> 7;
            int j = idx & 127;
            Ws[kk][j] = Wl[(k0 + kk) * DD + j];
        }
        __syncthreads();
#pragma unroll
        for (int k = 0; k < BK; k++) {
            float4 wv = *(const float4*)&Ws[k][tx * 4];
#pragma unroll
            for (int i = 0; i < 8; i++) {
                float a = Xs[ty * 8 + i][k];
                acc[i][0] += a * wv.x;
                acc[i][1] += a * wv.y;
                acc[i][2] += a * wv.z;
                acc[i][3] += a * wv.w;
            }
        }
        __syncthreads();
    }
#pragma unroll
    for (int i = 0; i < 8; i++) {
        int r = row0 + ty * 8 + i;
        if (r < NN)
            *(float4*)&g_h[r * DD + tx * 4] =
                make_float4(acc[i][0], acc[i][1], acc[i][2], acc[i][3]);
    }
}

// ---------------- fused: gather-agg + self-loop + residual + bias + LN + ReLU ----------------
// One warp per node; reads g_h (gather via CSR), updates g_xc in place.
__global__ void k_agg(const float* __restrict__ bl,
                      const float* __restrict__ gl,
                      const float* __restrict__ betal) {
    int warp = (blockIdx.x * blockDim.x + threadIdx.x) >> 5;
    if (warp >= NN) return;
    int lane = threadIdx.x & 31;
    int n = warp;
    int c4 = lane * 4;

    float4 acc = make_float4(0.f, 0.f, 0.f, 0.f);
    int j = g_off[n];
    int jend = g_off[n + 1];
    // unroll by 4 for MLP
    for (; j + 3 < jend; j += 4) {
        int s0 = g_esrc[j],     s1 = g_esrc[j + 1];
        int s2 = g_esrc[j + 2], s3 = g_esrc[j + 3];
        float c0 = g_ecoef[j],     c1 = g_ecoef[j + 1];
        float c2 = g_ecoef[j + 2], c3 = g_ecoef[j + 3];
        float4 h0 = *(const float4*)&g_h[s0 * DD + c4];
        float4 h1 = *(const float4*)&g_h[s1 * DD + c4];
        float4 h2 = *(const float4*)&g_h[s2 * DD + c4];
        float4 h3 = *(const float4*)&g_h[s3 * DD + c4];
        acc.x += h0.x * c0 + h1.x * c1 + h2.x * c2 + h3.x * c3;
        acc.y += h0.y * c0 + h1.y * c1 + h2.y * c2 + h3.y * c3;
        acc.z += h0.z * c0 + h1.z * c1 + h2.z * c2 + h3.z * c3;
        acc.w += h0.w * c0 + h1.w * c1 + h2.w * c2 + h3.w * c3;
    }
    for (; j < jend; j++) {
        int s0 = g_esrc[j];
        float c0 = g_ecoef[j];
        float4 h0 = *(const float4*)&g_h[s0 * DD + c4];
        acc.x += h0.x * c0;
        acc.y += h0.y * c0;
        acc.z += h0.z * c0;
        acc.w += h0.w * c0;
    }

    float di = g_dinv[n];
    float self = di * di;
    int base = n * DD + c4;
    float4 xv = *(const float4*)&g_xc[base];
    float4 hv = *(const float4*)&g_h[base];
    float4 bv = *(const float4*)&bl[c4];

    float v0 = xv.x + acc.x + hv.x * self + bv.x;
    float v1 = xv.y + acc.y + hv.y * self + bv.y;
    float v2 = xv.z + acc.z + hv.z * self + bv.z;
    float v3 = xv.w + acc.w + hv.w * self + bv.w;

    float s = v0 + v1 + v2 + v3;
#pragma unroll
    for (int o = 16; o > 0; o >>= 1) s += __shfl_xor_sync(0xffffffffu, s, o);
    float m = s * (1.0f / DD);

    float d0 = v0 - m, d1 = v1 - m, d2 = v2 - m, d3 = v3 - m;
    float sq = d0 * d0 + d1 * d1 + d2 * d2 + d3 * d3;
#pragma unroll
    for (int o = 16; o > 0; o >>= 1) sq += __shfl_xor_sync(0xffffffffu, sq, o);
    float inv = rsqrtf(sq * (1.0f / DD) + 1e-5f);

    float4 gv = *(const float4*)&gl[c4];
    float4 tv = *(const float4*)&betal[c4];
    float4 outv;
    outv.x = fmaxf(d0 * inv * gv.x + tv.x, 0.f);
    outv.y = fmaxf(d1 * inv * gv.y + tv.y, 0.f);
    outv.z = fmaxf(d2 * inv * gv.z + tv.z, 0.f);
    outv.w = fmaxf(d3 * inv * gv.w + tv.w, 0.f);
    *(float4*)&g_xc[base] = outv;
}

// ---------------- global mean pool: warp-chunked accumulation ----------------
#define CH 16
__global__ void k_pool(const int* __restrict__ batch) {
    int warp = (blockIdx.x * blockDim.x + threadIdx.x) >> 5;
    int lane = threadIdx.x & 31;
    int n0 = warp * CH;
    if (n0 >= NN) return;
    int n1 = n0 + CH;
    if (n1 > NN) n1 = NN;

    float4 acc = make_float4(0.f, 0.f, 0.f, 0.f);
    int cur = batch[n0];
    for (int n = n0; n < n1; n++) {
        int g = batch[n];
        if (g != cur) {
            float* sp = &g_sums[cur * DD + lane * 4];
            atomicAdd(sp + 0, acc.x);
            atomicAdd(sp + 1, acc.y);
            atomicAdd(sp + 2, acc.z);
            atomicAdd(sp + 3, acc.w);
            acc = make_float4(0.f, 0.f, 0.f, 0.f);
            cur = g;
        }
        float4 xv = *(const float4*)&g_xc[n * DD + lane * 4];
        acc.x += xv.x; acc.y += xv.y; acc.z += xv.z; acc.w += xv.w;
    }
    float* sp = &g_sums[cur * DD + lane * 4];
    atomicAdd(sp + 0, acc.x);
    atomicAdd(sp + 1, acc.y);
    atomicAdd(sp + 2, acc.z);
    atomicAdd(sp + 3, acc.w);
}

__global__ void k_out(float* __restrict__ out) {
    int i = blockIdx.x * blockDim.x + threadIdx.x;
    if (i < GG * DD) out[i] = g_sums[i] / fmaxf(g_cnt[i >> 7], 1.0f);
}

// ---------------- launch (host passes ONLY harness pointers) ----------------
extern "C" void kernel_launch(void* const* d_in, const int* in_sizes, int n_in,
                              void* d_out, int out_size) {
    const float* x = (const float*)d_in[0];
    const int* ei = (const int*)d_in[1];
    const int* batch = (const int*)d_in[2];
    const float* W = (const float*)d_in[3];
    const float* b = (const float*)d_in[4];
    const float* gamma = (const float*)d_in[5];
    const float* beta = (const float*)d_in[6];
    float* out = (float*)d_out;

    const int* src = ei;
    const int* dst = ei + EE;

    int nscan = (NN + SCB - 1) / SCB;  // 49

    k_init<<<(NN + 255) / 256, 256>>>();
    k_copy<<<(NN * DD / 4 + 255) / 256, 256>>>(x);
    k_deg<<<(EE + 255) / 256, 256>>>(dst);
    k_cnt<<<(NN + 255) / 256, 256>>>(batch);
    k_dinv<<<(NN + 255) / 256, 256>>>();
    k_scan1<<<nscan, SCB>>>();
    k_scan2<<<1, 32>>>(nscan);
    k_scan3<<<nscan + 1, SCB>>>();
    k_fill<<<(EE + 255) / 256, 256>>>(src, dst);

    for (int l = 0; l < LL; l++) {
        k_gemm<<<(NN + BM - 1) / BM, 256>>>(W + l * DD * DD);
        k_agg<<<(NN * 32 + 255) / 256, 256>>>(b + l * DD, gamma + l * DD, beta + l * DD);
    }

    k_pool<<<((NN + CH - 1) / CH * 32 + 255) / 256, 256>>>(batch);
    k_out<<<(GG * DD + 255) / 256, 256>>>(out);
}